// round 12
// baseline (speedup 1.0000x reference)
#include <cuda_runtime.h>
#include <math.h>

#define Nn 4096
#define Dd 256
#define Ss 32
#define Kk 4
#define KS 128           // K*S combined column dim
#define MAXNBR 256
#define ETA 0.5f

// ---- static device scratch (no allocations allowed) ----
__device__ int   g_cnt[Nn];
__device__ int   g_nbr[Nn][MAXNBR];      // 4 MB
__device__ float g_Z2[Nn][KS];           // 2 MB   Z[i][k*32+s]
__device__ float g_G2[Nn][KS];           // 2 MB
__device__ float g_Ut[KS][Dd];           // 128 KB U viewed [ks][d] (finalize)
__device__ float g_orth[16];

__device__ __constant__ int c_pk[10] = {0,0,0,0,1,1,1,2,2,3};
__device__ __constant__ int c_pl[10] = {0,1,2,3,1,2,3,2,3,3};

static __device__ __forceinline__ void fma4(float4& a, const float4& u, float g) {
    a.x += u.x * g; a.y += u.y * g; a.z += u.z * g; a.w += u.w * g;
}

// ===========================================================================
// K1: build_adj standalone. 2 warps per row (each scans 2048 cols = 2 chunks
// of 1024). Lane-local 32-bit masks from 8 independent LDG.128, warp prefix
// scan, cross-warp base via smem. No block-wide smem tax, low serial depth.
// grid 1024 x 256 (block = 4 rows).
// ===========================================================================
__global__ void build_adj(const float* __restrict__ mask) {
    __shared__ int wtot_s[8];
    int t = threadIdx.x;
    int warp = t >> 5, lane = t & 31;
    int row  = blockIdx.x * 4 + (warp >> 1);
    int half = warp & 1;
    const float4* m4 = (const float4*)(mask + (size_t)row * Nn) + half * 512;

    unsigned mk[2];
    int pre[2], cb[2];
    int wtot = 0;
#pragma unroll
    for (int c = 0; c < 2; c++) {
        float4 v[8];
#pragma unroll
        for (int q = 0; q < 8; q++)
            v[q] = __ldcs(&m4[c * 256 + lane * 8 + q]);
        unsigned m = 0;
#pragma unroll
        for (int q = 0; q < 8; q++) {
            if (v[q].x > 0.5f) m |= 1u << (q * 4 + 0);
            if (v[q].y > 0.5f) m |= 1u << (q * 4 + 1);
            if (v[q].z > 0.5f) m |= 1u << (q * 4 + 2);
            if (v[q].w > 0.5f) m |= 1u << (q * 4 + 3);
        }
        int cnt = __popc(m);
        int p = cnt;                                 // inclusive prefix
#pragma unroll
        for (int o = 1; o < 32; o <<= 1) {
            int nb = __shfl_up_sync(0xffffffffu, p, o);
            if (lane >= o) p += nb;
        }
        mk[c] = m; pre[c] = p; cb[c] = wtot;
        wtot += __shfl_sync(0xffffffffu, p, 31);
    }
    if (lane == 0) wtot_s[warp] = wtot;
    __syncthreads();
    int rowbase = half ? wtot_s[warp - 1] : 0;

#pragma unroll
    for (int c = 0; c < 2; c++) {
        int cnt  = __popc(mk[c]);
        int pos  = rowbase + cb[c] + pre[c] - cnt;
        int col0 = half * 2048 + c * 1024 + lane * 32;
        unsigned m = mk[c];
        while (m) {
            int bit = __ffs(m) - 1;
            m &= m - 1;
            if (pos < MAXNBR) g_nbr[row][pos] = col0 + bit;
            pos++;
        }
    }
    if (lane == 0 && half == 1) {
        int tot = rowbase + wtot;
        g_cnt[row] = tot < MAXNBR ? tot : MAXNBR;
    }
}

// ===========================================================================
// K2 (fused): blocks [0,128) compute_Z | [128,256) Ut transpose | [256,266) orth
// ===========================================================================
__global__ void prep2(const float* __restrict__ H, const float* __restrict__ U) {
    __shared__ __align__(16) char sbuf[32 * 1024];
    int b = blockIdx.x;
    int t = threadIdx.x;

    if (b < 128) {
        // ---- compute_Z: Z2[i][ks] = sum_d H[i][d] * U[k][d][s] ----
        float (*Hs)[Dd] = (float (*)[Dd])sbuf;       // 32 KB
        int i0 = b * 32;
        const float4* Hf4 = (const float4*)H;
        float4* Hs4 = (float4*)&Hs[0][0];
#pragma unroll
        for (int q = 0; q < 8; q++)
            Hs4[q * 256 + t] = Hf4[(size_t)i0 * 64 + q * 256 + t];
        __syncthreads();

        int tx = t & 31, ty = t >> 5;                // tx: ks4 group, ty: 8 row-groups
        int k = tx >> 3, s4 = tx & 7;
        const float4* Up = (const float4*)(U + ((size_t)k * Dd) * Ss + s4 * 4);
        int r0 = ty * 4;
        float4 a0 = {0,0,0,0}, a1 = {0,0,0,0}, a2 = {0,0,0,0}, a3 = {0,0,0,0};
#pragma unroll 4
        for (int d = 0; d < Dd; d++) {
            float4 u = Up[d * 8];                    // stride Ss floats = 8 float4
            fma4(a0, u, Hs[r0 + 0][d]);
            fma4(a1, u, Hs[r0 + 1][d]);
            fma4(a2, u, Hs[r0 + 2][d]);
            fma4(a3, u, Hs[r0 + 3][d]);
        }
        float4* Z4 = (float4*)&g_Z2[0][0];
        Z4[(size_t)(i0 + r0 + 0) * 32 + tx] = a0;
        Z4[(size_t)(i0 + r0 + 1) * 32 + tx] = a1;
        Z4[(size_t)(i0 + r0 + 2) * 32 + tx] = a2;
        Z4[(size_t)(i0 + r0 + 3) * 32 + tx] = a3;
    } else if (b < 256) {
        // ---- transpose U -> Ut[ks][d] ----
        int idx = (b - 128) * 256 + t;               // 32768 elems
        int k = idx >> 13;
        int r = idx & 8191;
        int d = r >> 5;
        int s = r & 31;
        g_Ut[k * Ss + s][d] = U[idx];
    } else {
        // ---- orth_pair p: gram block, 64-wide d-tiles ----
        float (*As)[65] = (float (*)[65])sbuf;                   // 8320 B
        float (*Bs)[65] = (float (*)[65])(sbuf + 8320);          // 8320 B
        float* red      = (float*)(sbuf + 16640);                // 1 KB
        int p = b - 256;
        int k = c_pk[p], l = c_pl[p];
        int ga = t >> 4, gb = t & 15;
        int a0 = ga * 2, b0 = gb * 2;
        float c00 = 0, c01 = 0, c10 = 0, c11 = 0;

        const float* Uk = U + (size_t)k * Dd * Ss;
        const float* Ul = U + (size_t)l * Dd * Ss;
        for (int d0 = 0; d0 < Dd; d0 += 64) {
            __syncthreads();
            for (int idx = t; idx < 32 * 64; idx += 256) {
                int d = idx >> 5, a = idx & 31;
                As[a][d] = Uk[(size_t)(d0 + d) * Ss + a];
                Bs[a][d] = Ul[(size_t)(d0 + d) * Ss + a];
            }
            __syncthreads();
#pragma unroll 4
            for (int d = 0; d < 64; d++) {
                float av0 = As[a0][d], av1 = As[a0 + 1][d];
                float bv0 = Bs[b0][d], bv1 = Bs[b0 + 1][d];
                c00 += av0 * bv0; c01 += av0 * bv1;
                c10 += av1 * bv0; c11 += av1 * bv1;
            }
        }

        float local;
        if (k == l) {
            float e;
            local = 0.f;
            e = c00 - ((a0     == b0    ) ? 1.f : 0.f); local += e * e;
            e = c01 - ((a0     == b0 + 1) ? 1.f : 0.f); local += e * e;
            e = c10 - ((a0 + 1 == b0    ) ? 1.f : 0.f); local += e * e;
            e = c11 - ((a0 + 1 == b0 + 1) ? 1.f : 0.f); local += e * e;
        } else {
            local = c00 * c00 + c01 * c01 + c10 * c10 + c11 * c11;
        }
        red[t] = local;
        __syncthreads();
        for (int o = 128; o; o >>= 1) {
            if (t < o) red[t] += red[t + o];
            __syncthreads();
        }
        if (t == 0) g_orth[p] = red[0];
    }
}

// ===========================================================================
// K3: sparse attention, online softmax, double-buffered full-tile prefetch
// (8 x LDG.128/lane). Block Nn (if present) sums the orth partials.
// ===========================================================================
__global__ void attn(const float* __restrict__ lp, float* __restrict__ loss_out) {
    __shared__ int   snbr[MAXNBR];
    __shared__ float Zt[Kk][32][33];                 // 33-pad: conflict-free both axes
    __shared__ float ew[Kk][32];
    __shared__ float zq[Kk][Ss];
    __shared__ int   scnt;

    int i = blockIdx.x;
    if (i >= Nn) {                                   // orth final sum (1 block)
        if (threadIdx.x == 0) {
            float s = 0.f;
            for (int p = 0; p < 10; p++) s += g_orth[p];
            loss_out[0] = s;
        }
        return;
    }

    int t = threadIdx.x;
    int k = t >> 5, lane = t & 31;

    if (t == 0) scnt = g_cnt[i];
    zq[k][lane] = g_Z2[i][t] * __expf(lp[t]);        // t == k*32+lane
    for (int j = lane; j < 32 * 33; j += 32) (&Zt[k][0][0])[j] = 0.f;
    __syncthreads();
    int cnt = scnt;
    for (int j = t; j < cnt; j += 128) snbr[j] = g_nbr[i][j];
    __syncthreads();

    const float inv = 0.17677669529663687f;          // 1/sqrt(32)
    int kbase = k << 5;
    int jj = lane >> 3;                              // row-group base 0..3
    int cc = (lane & 7) * 4;                         // float4 chunk 0..28
    float M = -3.0e38f, L = 0.f;
    float a0 = 0.f, a1 = 0.f, a2 = 0.f, a3 = 0.f;

    float4 pv[8];
#pragma unroll
    for (int it = 0; it < 8; it++) {
        int r = jj + 4 * it;
        if (r < cnt) pv[it] = *(const float4*)&g_Z2[snbr[r]][kbase + cc];
    }

    for (int t0 = 0; t0 < cnt; t0 += 32) {
        int tl = min(32, cnt - t0);

#pragma unroll
        for (int it = 0; it < 8; it++) {
            int r = jj + 4 * it;
            if (r < tl) {
                Zt[k][r][cc + 0] = pv[it].x; Zt[k][r][cc + 1] = pv[it].y;
                Zt[k][r][cc + 2] = pv[it].z; Zt[k][r][cc + 3] = pv[it].w;
            }
        }
        __syncwarp();

        int n0 = t0 + 32;
        if (n0 < cnt) {
#pragma unroll
            for (int it = 0; it < 8; it++) {
                int r = n0 + jj + 4 * it;
                if (r < cnt) pv[it] = *(const float4*)&g_Z2[snbr[r]][kbase + cc];
            }
        }

        float s0 = 0.f, s1 = 0.f;
#pragma unroll
        for (int s = 0; s < Ss; s += 2) {
            s0 += zq[k][s]     * Zt[k][lane][s];
            s1 += zq[k][s + 1] * Zt[k][lane][s + 1];
        }
        float sc = (lane < tl) ? (s0 + s1) * inv : -3.0e38f;

        float mt = sc;
#pragma unroll
        for (int o = 16; o; o >>= 1) mt = fmaxf(mt, __shfl_xor_sync(0xffffffffu, mt, o));
        float newM = fmaxf(M, mt);
        float e = (lane < tl) ? __expf(sc - newM) : 0.f;
        ew[k][lane] = e;
        float es = e;
#pragma unroll
        for (int o = 16; o; o >>= 1) es += __shfl_xor_sync(0xffffffffu, es, o);
        float scale = __expf(M - newM);
        L = L * scale + es;
        a0 *= scale; a1 *= scale; a2 *= scale; a3 *= scale;
        M = newM;
        __syncwarp();

#pragma unroll
        for (int j = 0; j < 32; j += 4) {
            a0 += ew[k][j + 0] * Zt[k][j + 0][lane];
            a1 += ew[k][j + 1] * Zt[k][j + 1][lane];
            a2 += ew[k][j + 2] * Zt[k][j + 2][lane];
            a3 += ew[k][j + 3] * Zt[k][j + 3][lane];
        }
        __syncwarp();
    }
    g_G2[i][t] = ((a0 + a1) + (a2 + a3)) / L;
}

// ===========================================================================
// K4: finalize. out = softthresh(H + ETA * G2 @ Ut, thr)
// ===========================================================================
__global__ void finalize(const float* __restrict__ H, const float* __restrict__ thr,
                         float* __restrict__ out) {
    __shared__ float Gs[32][KS];                     // 16 KB
    int b = blockIdx.x;
    int t = threadIdx.x;
    int i0 = b * 32;
    const float4* Gf4 = (const float4*)&g_G2[0][0];
    float4* Gs4 = (float4*)&Gs[0][0];
#pragma unroll
    for (int q = 0; q < 4; q++)
        Gs4[q * 256 + t] = Gf4[(size_t)i0 * 32 + q * 256 + t];
    __syncthreads();

    int tx = t & 63, ty = t >> 6;
    int r0 = ty * 8;
    float4 acc[8];
#pragma unroll
    for (int r = 0; r < 8; r++) acc[r] = make_float4(0, 0, 0, 0);

#pragma unroll 2
    for (int ks = 0; ks < KS; ks++) {
        float4 u = *(const float4*)&g_Ut[ks][tx * 4];
#pragma unroll
        for (int r = 0; r < 8; r++) fma4(acc[r], u, Gs[r0 + r][ks]);
    }

    const float4* Hf4 = (const float4*)H;
    const float4* Tf4 = (const float4*)thr;
    float4* Of4 = (float4*)out;
    float4 th = Tf4[tx];
#pragma unroll
    for (int r = 0; r < 8; r++) {
        int i = i0 + r0 + r;
        float4 h = Hf4[(size_t)i * 64 + tx];
        float4 v;
        v.x = h.x + ETA * acc[r].x;
        v.y = h.y + ETA * acc[r].y;
        v.z = h.z + ETA * acc[r].z;
        v.w = h.w + ETA * acc[r].w;
        float m;
        m = fmaxf(fabsf(v.x) - th.x, 0.f); v.x = copysignf(m, v.x);
        m = fmaxf(fabsf(v.y) - th.y, 0.f); v.y = copysignf(m, v.y);
        m = fmaxf(fabsf(v.z) - th.z, 0.f); v.z = copysignf(m, v.z);
        m = fmaxf(fabsf(v.w) - th.w, 0.f); v.w = copysignf(m, v.w);
        Of4[(size_t)i * 64 + tx] = v;
    }
}

// ---------------------------------------------------------------------------
extern "C" void kernel_launch(void* const* d_in, const int* in_sizes, int n_in,
                              void* d_out, int out_size) {
    const float* H    = (const float*)d_in[0];   // [N, D]
    const float* mask = (const float*)d_in[1];   // [N, N]
    const float* U    = (const float*)d_in[2];   // [K, D, S]
    const float* lp   = (const float*)d_in[3];   // [K, S]
    const float* thr  = (const float*)d_in[4];   // [D]
    float* out = (float*)d_out;

    bool want_loss = (out_size > Nn * Dd);
    build_adj<<<1024, 256>>>(mask);
    prep2<<<266, 256>>>(H, U);
    attn<<<want_loss ? Nn + 1 : Nn, 128>>>(lp, out + (size_t)Nn * Dd);
    finalize<<<128, 256>>>(H, thr, out);
}

// round 13
// speedup vs baseline: 1.0191x; 1.0191x over previous
#include <cuda_runtime.h>
#include <math.h>

#define Nn 4096
#define Dd 256
#define Ss 32
#define Kk 4
#define KS 128           // K*S combined column dim
#define MAXNBR 256
#define ETA 0.5f

// ---- static device scratch (no allocations allowed) ----
__device__ int   g_cnt[Nn];
__device__ int   g_nbr[Nn][MAXNBR];      // 4 MB
__device__ float g_Z2[Nn][KS];           // 2 MB   Z[i][k*32+s]
__device__ float g_Ut[KS][Dd];           // 128 KB U viewed [ks][d]
__device__ float g_orth[16];

__device__ __constant__ int c_pk[10] = {0,0,0,0,1,1,1,2,2,3};
__device__ __constant__ int c_pl[10] = {0,1,2,3,1,2,3,2,3,3};

static __device__ __forceinline__ void fma4(float4& a, const float4& u, float g) {
    a.x += u.x * g; a.y += u.y * g; a.z += u.z * g; a.w += u.w * g;
}

// ===========================================================================
// K1: build_adj. 2 warps per row (each scans 2048 cols). Lane-local 32-bit
// masks from 8 independent LDG.128, warp prefix scan, cross-warp base in smem.
// grid 1024 x 256 (block = 4 rows).
// ===========================================================================
__global__ void build_adj(const float* __restrict__ mask) {
    __shared__ int wtot_s[8];
    int t = threadIdx.x;
    int warp = t >> 5, lane = t & 31;
    int row  = blockIdx.x * 4 + (warp >> 1);
    int half = warp & 1;
    const float4* m4 = (const float4*)(mask + (size_t)row * Nn) + half * 512;

    unsigned mk[2];
    int pre[2], cb[2];
    int wtot = 0;
#pragma unroll
    for (int c = 0; c < 2; c++) {
        float4 v[8];
#pragma unroll
        for (int q = 0; q < 8; q++)
            v[q] = __ldcs(&m4[c * 256 + lane * 8 + q]);
        unsigned m = 0;
#pragma unroll
        for (int q = 0; q < 8; q++) {
            if (v[q].x > 0.5f) m |= 1u << (q * 4 + 0);
            if (v[q].y > 0.5f) m |= 1u << (q * 4 + 1);
            if (v[q].z > 0.5f) m |= 1u << (q * 4 + 2);
            if (v[q].w > 0.5f) m |= 1u << (q * 4 + 3);
        }
        int cnt = __popc(m);
        int p = cnt;                                 // inclusive prefix
#pragma unroll
        for (int o = 1; o < 32; o <<= 1) {
            int nb = __shfl_up_sync(0xffffffffu, p, o);
            if (lane >= o) p += nb;
        }
        mk[c] = m; pre[c] = p; cb[c] = wtot;
        wtot += __shfl_sync(0xffffffffu, p, 31);
    }
    if (lane == 0) wtot_s[warp] = wtot;
    __syncthreads();
    int rowbase = half ? wtot_s[warp - 1] : 0;

#pragma unroll
    for (int c = 0; c < 2; c++) {
        int cnt  = __popc(mk[c]);
        int pos  = rowbase + cb[c] + pre[c] - cnt;
        int col0 = half * 2048 + c * 1024 + lane * 32;
        unsigned m = mk[c];
        while (m) {
            int bit = __ffs(m) - 1;
            m &= m - 1;
            if (pos < MAXNBR) g_nbr[row][pos] = col0 + bit;
            pos++;
        }
    }
    if (lane == 0 && half == 1) {
        int tot = rowbase + wtot;
        g_cnt[row] = tot < MAXNBR ? tot : MAXNBR;
    }
}

// ===========================================================================
// K2 (fused): blocks [0,128) compute_Z | [128,256) Ut transpose | [256,266) orth
// ===========================================================================
__global__ void prep2(const float* __restrict__ H, const float* __restrict__ U) {
    __shared__ __align__(16) char sbuf[32 * 1024];
    int b = blockIdx.x;
    int t = threadIdx.x;

    if (b < 128) {
        // ---- compute_Z: Z2[i][ks] = sum_d H[i][d] * U[k][d][s] ----
        float (*Hs)[Dd] = (float (*)[Dd])sbuf;       // 32 KB
        int i0 = b * 32;
        const float4* Hf4 = (const float4*)H;
        float4* Hs4 = (float4*)&Hs[0][0];
#pragma unroll
        for (int q = 0; q < 8; q++)
            Hs4[q * 256 + t] = Hf4[(size_t)i0 * 64 + q * 256 + t];
        __syncthreads();

        int tx = t & 31, ty = t >> 5;                // tx: ks4 group, ty: 8 row-groups
        int k = tx >> 3, s4 = tx & 7;
        const float4* Up = (const float4*)(U + ((size_t)k * Dd) * Ss + s4 * 4);
        int r0 = ty * 4;
        float4 a0 = {0,0,0,0}, a1 = {0,0,0,0}, a2 = {0,0,0,0}, a3 = {0,0,0,0};
#pragma unroll 4
        for (int d = 0; d < Dd; d++) {
            float4 u = Up[d * 8];                    // stride Ss floats = 8 float4
            fma4(a0, u, Hs[r0 + 0][d]);
            fma4(a1, u, Hs[r0 + 1][d]);
            fma4(a2, u, Hs[r0 + 2][d]);
            fma4(a3, u, Hs[r0 + 3][d]);
        }
        float4* Z4 = (float4*)&g_Z2[0][0];
        Z4[(size_t)(i0 + r0 + 0) * 32 + tx] = a0;
        Z4[(size_t)(i0 + r0 + 1) * 32 + tx] = a1;
        Z4[(size_t)(i0 + r0 + 2) * 32 + tx] = a2;
        Z4[(size_t)(i0 + r0 + 3) * 32 + tx] = a3;
    } else if (b < 256) {
        // ---- transpose U -> Ut[ks][d] ----
        int idx = (b - 128) * 256 + t;               // 32768 elems
        int k = idx >> 13;
        int r = idx & 8191;
        int d = r >> 5;
        int s = r & 31;
        g_Ut[k * Ss + s][d] = U[idx];
    } else {
        // ---- orth_pair p: gram block, 64-wide d-tiles ----
        float (*As)[65] = (float (*)[65])sbuf;                   // 8320 B
        float (*Bs)[65] = (float (*)[65])(sbuf + 8320);          // 8320 B
        float* red      = (float*)(sbuf + 16640);                // 1 KB
        int p = b - 256;
        int k = c_pk[p], l = c_pl[p];
        int ga = t >> 4, gb = t & 15;
        int a0 = ga * 2, b0 = gb * 2;
        float c00 = 0, c01 = 0, c10 = 0, c11 = 0;

        const float* Uk = U + (size_t)k * Dd * Ss;
        const float* Ul = U + (size_t)l * Dd * Ss;
        for (int d0 = 0; d0 < Dd; d0 += 64) {
            __syncthreads();
            for (int idx = t; idx < 32 * 64; idx += 256) {
                int d = idx >> 5, a = idx & 31;
                As[a][d] = Uk[(size_t)(d0 + d) * Ss + a];
                Bs[a][d] = Ul[(size_t)(d0 + d) * Ss + a];
            }
            __syncthreads();
#pragma unroll 4
            for (int d = 0; d < 64; d++) {
                float av0 = As[a0][d], av1 = As[a0 + 1][d];
                float bv0 = Bs[b0][d], bv1 = Bs[b0 + 1][d];
                c00 += av0 * bv0; c01 += av0 * bv1;
                c10 += av1 * bv0; c11 += av1 * bv1;
            }
        }

        float local;
        if (k == l) {
            float e;
            local = 0.f;
            e = c00 - ((a0     == b0    ) ? 1.f : 0.f); local += e * e;
            e = c01 - ((a0     == b0 + 1) ? 1.f : 0.f); local += e * e;
            e = c10 - ((a0 + 1 == b0    ) ? 1.f : 0.f); local += e * e;
            e = c11 - ((a0 + 1 == b0 + 1) ? 1.f : 0.f); local += e * e;
        } else {
            local = c00 * c00 + c01 * c01 + c10 * c10 + c11 * c11;
        }
        red[t] = local;
        __syncthreads();
        for (int o = 128; o; o >>= 1) {
            if (t < o) red[t] += red[t + o];
            __syncthreads();
        }
        if (t == 0) g_orth[p] = red[0];
    }
}

// ===========================================================================
// K3: sparse attention + FUSED finalize epilogue.
// Main loop: online softmax over neighbor tiles (double-buffered prefetch).
// Epilogue: G row (128 vals) staged in smem; each thread computes its 2
// output dims via 128-step dot vs Ut (float2, lane-contiguous, L1-resident),
// then soft-threshold and store. No g_G2 round-trip, no finalize launch.
// ===========================================================================
__global__ void attn(const float* __restrict__ lp, const float* __restrict__ H,
                     const float* __restrict__ thr, float* __restrict__ out,
                     float* __restrict__ loss_out) {
    __shared__ int   snbr[MAXNBR];
    __shared__ float Zt[Kk][32][33];                 // 33-pad: conflict-free both axes
    __shared__ float ew[Kk][32];
    __shared__ float zq[Kk][Ss];
    __shared__ float gsh[KS];
    __shared__ int   scnt;

    int i = blockIdx.x;
    if (i >= Nn) {                                   // orth final sum (1 block)
        if (threadIdx.x == 0) {
            float s = 0.f;
            for (int p = 0; p < 10; p++) s += g_orth[p];
            loss_out[0] = s;
        }
        return;
    }

    int t = threadIdx.x;
    int k = t >> 5, lane = t & 31;

    if (t == 0) scnt = g_cnt[i];
    zq[k][lane] = g_Z2[i][t] * __expf(lp[t]);        // t == k*32+lane
    for (int j = lane; j < 32 * 33; j += 32) (&Zt[k][0][0])[j] = 0.f;
    __syncthreads();
    int cnt = scnt;
    for (int j = t; j < cnt; j += 128) snbr[j] = g_nbr[i][j];
    __syncthreads();

    const float inv = 0.17677669529663687f;          // 1/sqrt(32)
    int kbase = k << 5;
    int jj = lane >> 3;                              // row-group base 0..3
    int cc = (lane & 7) * 4;                         // float4 chunk 0..28
    float M = -3.0e38f, L = 0.f;
    float a0 = 0.f, a1 = 0.f, a2 = 0.f, a3 = 0.f;

    float4 pv[8];
#pragma unroll
    for (int it = 0; it < 8; it++) {
        int r = jj + 4 * it;
        if (r < cnt) pv[it] = *(const float4*)&g_Z2[snbr[r]][kbase + cc];
    }

    for (int t0 = 0; t0 < cnt; t0 += 32) {
        int tl = min(32, cnt - t0);

#pragma unroll
        for (int it = 0; it < 8; it++) {
            int r = jj + 4 * it;
            if (r < tl) {
                Zt[k][r][cc + 0] = pv[it].x; Zt[k][r][cc + 1] = pv[it].y;
                Zt[k][r][cc + 2] = pv[it].z; Zt[k][r][cc + 3] = pv[it].w;
            }
        }
        __syncwarp();

        int n0 = t0 + 32;
        if (n0 < cnt) {
#pragma unroll
            for (int it = 0; it < 8; it++) {
                int r = n0 + jj + 4 * it;
                if (r < cnt) pv[it] = *(const float4*)&g_Z2[snbr[r]][kbase + cc];
            }
        }

        float s0 = 0.f, s1 = 0.f;
#pragma unroll
        for (int s = 0; s < Ss; s += 2) {
            s0 += zq[k][s]     * Zt[k][lane][s];
            s1 += zq[k][s + 1] * Zt[k][lane][s + 1];
        }
        float sc = (lane < tl) ? (s0 + s1) * inv : -3.0e38f;

        float mt = sc;
#pragma unroll
        for (int o = 16; o; o >>= 1) mt = fmaxf(mt, __shfl_xor_sync(0xffffffffu, mt, o));
        float newM = fmaxf(M, mt);
        float e = (lane < tl) ? __expf(sc - newM) : 0.f;
        ew[k][lane] = e;
        float es = e;
#pragma unroll
        for (int o = 16; o; o >>= 1) es += __shfl_xor_sync(0xffffffffu, es, o);
        float scale = __expf(M - newM);
        L = L * scale + es;
        a0 *= scale; a1 *= scale; a2 *= scale; a3 *= scale;
        M = newM;
        __syncwarp();

#pragma unroll
        for (int j = 0; j < 32; j += 4) {
            a0 += ew[k][j + 0] * Zt[k][j + 0][lane];
            a1 += ew[k][j + 1] * Zt[k][j + 1][lane];
            a2 += ew[k][j + 2] * Zt[k][j + 2][lane];
            a3 += ew[k][j + 3] * Zt[k][j + 3][lane];
        }
        __syncwarp();
    }
    gsh[t] = ((a0 + a1) + (a2 + a3)) / L;
    __syncthreads();

    // ---- fused finalize: out[i][2t..2t+1] ----
    // Issue H/thr loads early; 4 accumulators (2 per output) break RAW chains.
    float2 h  = ((const float2*)H)[(size_t)i * 128 + t];
    float2 th = ((const float2*)thr)[t];
    float x0 = 0.f, x1 = 0.f, y0 = 0.f, y1 = 0.f;
#pragma unroll 8
    for (int ks = 0; ks < KS; ks += 2) {
        float g0 = gsh[ks], g1 = gsh[ks + 1];
        float2 u0 = *(const float2*)&g_Ut[ks][2 * t];
        float2 u1 = *(const float2*)&g_Ut[ks + 1][2 * t];
        x0 += u0.x * g0; y0 += u0.y * g0;
        x1 += u1.x * g1; y1 += u1.y * g1;
    }
    float2 v;
    v.x = h.x + ETA * (x0 + x1);
    v.y = h.y + ETA * (y0 + y1);
    float m;
    m = fmaxf(fabsf(v.x) - th.x, 0.f); v.x = copysignf(m, v.x);
    m = fmaxf(fabsf(v.y) - th.y, 0.f); v.y = copysignf(m, v.y);
    ((float2*)out)[(size_t)i * 128 + t] = v;
}

// ---------------------------------------------------------------------------
extern "C" void kernel_launch(void* const* d_in, const int* in_sizes, int n_in,
                              void* d_out, int out_size) {
    const float* H    = (const float*)d_in[0];   // [N, D]
    const float* mask = (const float*)d_in[1];   // [N, N]
    const float* U    = (const float*)d_in[2];   // [K, D, S]
    const float* lp   = (const float*)d_in[3];   // [K, S]
    const float* thr  = (const float*)d_in[4];   // [D]
    float* out = (float*)d_out;

    bool want_loss = (out_size > Nn * Dd);
    build_adj<<<1024, 256>>>(mask);
    prep2<<<266, 256>>>(H, U);
    attn<<<want_loss ? Nn + 1 : Nn, 128>>>(lp, H, thr, out, out + (size_t)Nn * Dd);
}

// round 14
// speedup vs baseline: 1.0453x; 1.0257x over previous
#include <cuda_runtime.h>
#include <math.h>

#define Nn 4096
#define Dd 256
#define Ss 32
#define Kk 4
#define KS 128           // K*S combined column dim
#define MAXNBR 256
#define ETA 0.5f

// ---- static device scratch (no allocations allowed) ----
__device__ int   g_cnt[Nn];
__device__ int   g_nbr[Nn][MAXNBR];      // 4 MB
__device__ float g_Z2[Nn][KS];           // 2 MB   Z[i][k*32+s]
__device__ float g_G2[Nn][KS];           // 2 MB
__device__ float g_Ut[KS][Dd];           // 128 KB U viewed [ks][d]
__device__ float g_orth[16];

__device__ __constant__ int c_pk[10] = {0,0,0,0,1,1,1,2,2,3};
__device__ __constant__ int c_pl[10] = {0,1,2,3,1,2,3,2,3,3};

static __device__ __forceinline__ void fma4(float4& a, const float4& u, float g) {
    a.x += u.x * g; a.y += u.y * g; a.z += u.z * g; a.w += u.w * g;
}

// ===========================================================================
// K1: build_adj. 2 warps per row, COALESCED loads: for each q the warp reads
// 32 consecutive float4 (512B). Lane owns an interleaved 32-element column
// set; mask bit b=q*4+j -> col q*128 + lane*4 + j. Deterministic order.
// grid 1024 x 256 (block = 4 rows).
// ===========================================================================
__global__ void build_adj(const float* __restrict__ mask) {
    __shared__ int wtot_s[8];
    int t = threadIdx.x;
    int warp = t >> 5, lane = t & 31;
    int row  = blockIdx.x * 4 + (warp >> 1);
    int half = warp & 1;
    const float4* m4 = (const float4*)(mask + (size_t)row * Nn) + half * 512;

    unsigned mk[2];
    int pre[2], cb[2];
    int wtot = 0;
#pragma unroll
    for (int c = 0; c < 2; c++) {
        float4 v[8];
#pragma unroll
        for (int q = 0; q < 8; q++)
            v[q] = __ldcs(&m4[c * 256 + q * 32 + lane]);   // coalesced
        unsigned m = 0;
#pragma unroll
        for (int q = 0; q < 8; q++) {
            if (v[q].x > 0.5f) m |= 1u << (q * 4 + 0);
            if (v[q].y > 0.5f) m |= 1u << (q * 4 + 1);
            if (v[q].z > 0.5f) m |= 1u << (q * 4 + 2);
            if (v[q].w > 0.5f) m |= 1u << (q * 4 + 3);
        }
        int cnt = __popc(m);
        int p = cnt;                                 // inclusive prefix
#pragma unroll
        for (int o = 1; o < 32; o <<= 1) {
            int nb = __shfl_up_sync(0xffffffffu, p, o);
            if (lane >= o) p += nb;
        }
        mk[c] = m; pre[c] = p; cb[c] = wtot;
        wtot += __shfl_sync(0xffffffffu, p, 31);
    }
    if (lane == 0) wtot_s[warp] = wtot;
    __syncthreads();
    int rowbase = half ? wtot_s[warp - 1] : 0;

#pragma unroll
    for (int c = 0; c < 2; c++) {
        int cnt  = __popc(mk[c]);
        int pos  = rowbase + cb[c] + pre[c] - cnt;
        int col0 = half * 2048 + c * 1024 + lane * 4;
        unsigned m = mk[c];
        while (m) {
            int b = __ffs(m) - 1;
            m &= m - 1;
            int col = col0 + (b >> 2) * 128 + (b & 3);
            if (pos < MAXNBR) g_nbr[row][pos] = col;
            pos++;
        }
    }
    if (lane == 0 && half == 1) {
        int tot = rowbase + wtot;
        g_cnt[row] = tot < MAXNBR ? tot : MAXNBR;
    }
}

// ===========================================================================
// K2 (fused): blocks [0,128) compute_Z | [128,256) Ut transpose | [256,266) orth
// ===========================================================================
__global__ void prep2(const float* __restrict__ H, const float* __restrict__ U) {
    __shared__ __align__(16) char sbuf[32 * 1024];
    int b = blockIdx.x;
    int t = threadIdx.x;

    if (b < 128) {
        // ---- compute_Z: Z2[i][ks] = sum_d H[i][d] * U[k][d][s] ----
        float (*Hs)[Dd] = (float (*)[Dd])sbuf;       // 32 KB
        int i0 = b * 32;
        const float4* Hf4 = (const float4*)H;
        float4* Hs4 = (float4*)&Hs[0][0];
#pragma unroll
        for (int q = 0; q < 8; q++)
            Hs4[q * 256 + t] = Hf4[(size_t)i0 * 64 + q * 256 + t];
        __syncthreads();

        int tx = t & 31, ty = t >> 5;                // tx: ks4 group, ty: 8 row-groups
        int k = tx >> 3, s4 = tx & 7;
        const float4* Up = (const float4*)(U + ((size_t)k * Dd) * Ss + s4 * 4);
        int r0 = ty * 4;
        float4 a0 = {0,0,0,0}, a1 = {0,0,0,0}, a2 = {0,0,0,0}, a3 = {0,0,0,0};
#pragma unroll 4
        for (int d = 0; d < Dd; d++) {
            float4 u = Up[d * 8];                    // stride Ss floats = 8 float4
            fma4(a0, u, Hs[r0 + 0][d]);
            fma4(a1, u, Hs[r0 + 1][d]);
            fma4(a2, u, Hs[r0 + 2][d]);
            fma4(a3, u, Hs[r0 + 3][d]);
        }
        float4* Z4 = (float4*)&g_Z2[0][0];
        Z4[(size_t)(i0 + r0 + 0) * 32 + tx] = a0;
        Z4[(size_t)(i0 + r0 + 1) * 32 + tx] = a1;
        Z4[(size_t)(i0 + r0 + 2) * 32 + tx] = a2;
        Z4[(size_t)(i0 + r0 + 3) * 32 + tx] = a3;
    } else if (b < 256) {
        // ---- transpose U -> Ut[ks][d] ----
        int idx = (b - 128) * 256 + t;               // 32768 elems
        int k = idx >> 13;
        int r = idx & 8191;
        int d = r >> 5;
        int s = r & 31;
        g_Ut[k * Ss + s][d] = U[idx];
    } else {
        // ---- orth_pair p: gram block, 64-wide d-tiles ----
        float (*As)[65] = (float (*)[65])sbuf;                   // 8320 B
        float (*Bs)[65] = (float (*)[65])(sbuf + 8320);          // 8320 B
        float* red      = (float*)(sbuf + 16640);                // 1 KB
        int p = b - 256;
        int k = c_pk[p], l = c_pl[p];
        int ga = t >> 4, gb = t & 15;
        int a0 = ga * 2, b0 = gb * 2;
        float c00 = 0, c01 = 0, c10 = 0, c11 = 0;

        const float* Uk = U + (size_t)k * Dd * Ss;
        const float* Ul = U + (size_t)l * Dd * Ss;
        for (int d0 = 0; d0 < Dd; d0 += 64) {
            __syncthreads();
            for (int idx = t; idx < 32 * 64; idx += 256) {
                int d = idx >> 5, a = idx & 31;
                As[a][d] = Uk[(size_t)(d0 + d) * Ss + a];
                Bs[a][d] = Ul[(size_t)(d0 + d) * Ss + a];
            }
            __syncthreads();
#pragma unroll 4
            for (int d = 0; d < 64; d++) {
                float av0 = As[a0][d], av1 = As[a0 + 1][d];
                float bv0 = Bs[b0][d], bv1 = Bs[b0 + 1][d];
                c00 += av0 * bv0; c01 += av0 * bv1;
                c10 += av1 * bv0; c11 += av1 * bv1;
            }
        }

        float local;
        if (k == l) {
            float e;
            local = 0.f;
            e = c00 - ((a0     == b0    ) ? 1.f : 0.f); local += e * e;
            e = c01 - ((a0     == b0 + 1) ? 1.f : 0.f); local += e * e;
            e = c10 - ((a0 + 1 == b0    ) ? 1.f : 0.f); local += e * e;
            e = c11 - ((a0 + 1 == b0 + 1) ? 1.f : 0.f); local += e * e;
        } else {
            local = c00 * c00 + c01 * c01 + c10 * c10 + c11 * c11;
        }
        red[t] = local;
        __syncthreads();
        for (int o = 128; o; o >>= 1) {
            if (t < o) red[t] += red[t + o];
            __syncthreads();
        }
        if (t == 0) g_orth[p] = red[0];
    }
}

// ===========================================================================
// K3: sparse attention, online softmax, double-buffered full-tile prefetch
// (8 x LDG.128/lane). Writes g_G2. Block Nn (if present) sums orth partials.
// ===========================================================================
__global__ void attn(const float* __restrict__ lp, float* __restrict__ loss_out) {
    __shared__ int   snbr[MAXNBR];
    __shared__ float Zt[Kk][32][33];                 // 33-pad: conflict-free both axes
    __shared__ float ew[Kk][32];
    __shared__ float zq[Kk][Ss];
    __shared__ int   scnt;

    int i = blockIdx.x;
    if (i >= Nn) {                                   // orth final sum (1 block)
        if (threadIdx.x == 0) {
            float s = 0.f;
            for (int p = 0; p < 10; p++) s += g_orth[p];
            loss_out[0] = s;
        }
        return;
    }

    int t = threadIdx.x;
    int k = t >> 5, lane = t & 31;

    if (t == 0) scnt = g_cnt[i];
    zq[k][lane] = g_Z2[i][t] * __expf(lp[t]);        // t == k*32+lane
    for (int j = lane; j < 32 * 33; j += 32) (&Zt[k][0][0])[j] = 0.f;
    __syncthreads();
    int cnt = scnt;
    for (int j = t; j < cnt; j += 128) snbr[j] = g_nbr[i][j];
    __syncthreads();

    const float inv = 0.17677669529663687f;          // 1/sqrt(32)
    int kbase = k << 5;
    int jj = lane >> 3;                              // row-group base 0..3
    int cc = (lane & 7) * 4;                         // float4 chunk 0..28
    float M = -3.0e38f, L = 0.f;
    float a0 = 0.f, a1 = 0.f, a2 = 0.f, a3 = 0.f;

    float4 pv[8];
#pragma unroll
    for (int it = 0; it < 8; it++) {
        int r = jj + 4 * it;
        if (r < cnt) pv[it] = *(const float4*)&g_Z2[snbr[r]][kbase + cc];
    }

    for (int t0 = 0; t0 < cnt; t0 += 32) {
        int tl = min(32, cnt - t0);

#pragma unroll
        for (int it = 0; it < 8; it++) {
            int r = jj + 4 * it;
            if (r < tl) {
                Zt[k][r][cc + 0] = pv[it].x; Zt[k][r][cc + 1] = pv[it].y;
                Zt[k][r][cc + 2] = pv[it].z; Zt[k][r][cc + 3] = pv[it].w;
            }
        }
        __syncwarp();

        int n0 = t0 + 32;
        if (n0 < cnt) {
#pragma unroll
            for (int it = 0; it < 8; it++) {
                int r = n0 + jj + 4 * it;
                if (r < cnt) pv[it] = *(const float4*)&g_Z2[snbr[r]][kbase + cc];
            }
        }

        float s0 = 0.f, s1 = 0.f;
#pragma unroll
        for (int s = 0; s < Ss; s += 2) {
            s0 += zq[k][s]     * Zt[k][lane][s];
            s1 += zq[k][s + 1] * Zt[k][lane][s + 1];
        }
        float sc = (lane < tl) ? (s0 + s1) * inv : -3.0e38f;

        float mt = sc;
#pragma unroll
        for (int o = 16; o; o >>= 1) mt = fmaxf(mt, __shfl_xor_sync(0xffffffffu, mt, o));
        float newM = fmaxf(M, mt);
        float e = (lane < tl) ? __expf(sc - newM) : 0.f;
        ew[k][lane] = e;
        float es = e;
#pragma unroll
        for (int o = 16; o; o >>= 1) es += __shfl_xor_sync(0xffffffffu, es, o);
        float scale = __expf(M - newM);
        L = L * scale + es;
        a0 *= scale; a1 *= scale; a2 *= scale; a3 *= scale;
        M = newM;
        __syncwarp();

#pragma unroll
        for (int j = 0; j < 32; j += 4) {
            a0 += ew[k][j + 0] * Zt[k][j + 0][lane];
            a1 += ew[k][j + 1] * Zt[k][j + 1][lane];
            a2 += ew[k][j + 2] * Zt[k][j + 2][lane];
            a3 += ew[k][j + 3] * Zt[k][j + 3][lane];
        }
        __syncwarp();
    }
    g_G2[i][t] = ((a0 + a1) + (a2 + a3)) / L;
}

// ===========================================================================
// K4: finalize, 8-row tiles, grid 512 (high parallelism). Thread = 2 rows x
// float4 of d. out = softthresh(H + ETA * G2 @ Ut, thr)
// ===========================================================================
__global__ void finalize(const float* __restrict__ H, const float* __restrict__ thr,
                         float* __restrict__ out) {
    __shared__ float Gs[8][KS];                      // 4 KB
    int b = blockIdx.x;
    int t = threadIdx.x;
    int i0 = b * 8;
    ((float4*)&Gs[0][0])[t] = ((const float4*)&g_G2[0][0])[(size_t)i0 * 32 + t];
    __syncthreads();

    int tx = t & 63, ty = t >> 6;                    // tx: d4 group, ty: 2-row group
    int r0 = ty * 2;
    float4 acc0 = {0,0,0,0}, acc1 = {0,0,0,0};
#pragma unroll 4
    for (int ks = 0; ks < KS; ks++) {
        float4 u = *(const float4*)&g_Ut[ks][tx * 4];
        fma4(acc0, u, Gs[r0 + 0][ks]);
        fma4(acc1, u, Gs[r0 + 1][ks]);
    }

    const float4* Hf4 = (const float4*)H;
    const float4* Tf4 = (const float4*)thr;
    float4* Of4 = (float4*)out;
    float4 th = Tf4[tx];
#pragma unroll
    for (int r = 0; r < 2; r++) {
        int i = i0 + r0 + r;
        float4 a = r ? acc1 : acc0;
        float4 h = Hf4[(size_t)i * 64 + tx];
        float4 v;
        v.x = h.x + ETA * a.x;
        v.y = h.y + ETA * a.y;
        v.z = h.z + ETA * a.z;
        v.w = h.w + ETA * a.w;
        float m;
        m = fmaxf(fabsf(v.x) - th.x, 0.f); v.x = copysignf(m, v.x);
        m = fmaxf(fabsf(v.y) - th.y, 0.f); v.y = copysignf(m, v.y);
        m = fmaxf(fabsf(v.z) - th.z, 0.f); v.z = copysignf(m, v.z);
        m = fmaxf(fabsf(v.w) - th.w, 0.f); v.w = copysignf(m, v.w);
        Of4[(size_t)i * 64 + tx] = v;
    }
}

// ---------------------------------------------------------------------------
extern "C" void kernel_launch(void* const* d_in, const int* in_sizes, int n_in,
                              void* d_out, int out_size) {
    const float* H    = (const float*)d_in[0];   // [N, D]
    const float* mask = (const float*)d_in[1];   // [N, N]
    const float* U    = (const float*)d_in[2];   // [K, D, S]
    const float* lp   = (const float*)d_in[3];   // [K, S]
    const float* thr  = (const float*)d_in[4];   // [D]
    float* out = (float*)d_out;

    bool want_loss = (out_size > Nn * Dd);
    build_adj<<<1024, 256>>>(mask);
    prep2<<<266, 256>>>(H, U);
    attn<<<want_loss ? Nn + 1 : Nn, 128>>>(lp, out + (size_t)Nn * Dd);
    finalize<<<512, 256>>>(H, thr, out);
}

// round 15
// speedup vs baseline: 1.1545x; 1.1045x over previous
#include <cuda_runtime.h>
#include <math.h>

#define Nn 4096
#define Dd 256
#define Ss 32
#define Kk 4
#define KS 128           // K*S combined column dim
#define MAXNBR 256
#define ETA 0.5f

// grid regions
#define NB_ADJ  2048     // 2 rows per block
#define NB_Z    256      // 16 rows per block
#define NB_UT   128      // 256 elems per block
#define NB_ORTH 10
#define N_PREP  (NB_ADJ + NB_Z + NB_UT + NB_ORTH)   // 2442
#define B_E     N_PREP                              // orth-sum block
#define B_ATTN0 (N_PREP + 1)
#define B_FIN0  (B_ATTN0 + Nn)
#define NB_FIN  512
#define GRID    (B_FIN0 + NB_FIN)                   // 7051
#define FIN_PART (NB_FIN + 1)                       // fin blocks + E

// ---- static device scratch (no allocations; zero-initialized at load) ----
__device__ int   g_prep_ctr;
__device__ int   g_attn_ctr;
__device__ int   g_fin_ctr;
__device__ int   g_cnt[Nn];
__device__ int   g_nbr[Nn][MAXNBR];      // 4 MB
__device__ float g_Z2[Nn][KS];           // 2 MB
__device__ float g_G2[Nn][KS];           // 2 MB
__device__ float g_Ut[KS][Dd];           // 128 KB
__device__ float g_orth[16];

__device__ __constant__ int c_pk[10] = {0,0,0,0,1,1,1,2,2,3};
__device__ __constant__ int c_pl[10] = {0,1,2,3,1,2,3,2,3,3};

static __device__ __forceinline__ void fma4(float4& a, const float4& u, float g) {
    a.x += u.x * g; a.y += u.y * g; a.z += u.z * g; a.w += u.w * g;
}

// ---- gpu-scope release/acquire primitives ----
static __device__ __forceinline__ int ld_acq(const int* p) {
    int v; asm volatile("ld.acquire.gpu.b32 %0, [%1];" : "=r"(v) : "l"(p) : "memory");
    return v;
}
static __device__ __forceinline__ void red_rel_add(int* p, int v) {
    asm volatile("red.release.gpu.add.s32 [%0], %1;" :: "l"(p), "r"(v) : "memory");
}
static __device__ __forceinline__ int atom_rel_add(int* p, int v) {
    int o; asm volatile("atom.release.gpu.add.s32 %0, [%1], %2;"
                        : "=r"(o) : "l"(p), "r"(v) : "memory");
    return o;
}
static __device__ __forceinline__ void spin_until(int* p, int target) {
    int ns = 64;
    while (ld_acq(p) != target) { __nanosleep(ns); if (ns < 1024) ns <<= 1; }
}

// ===========================================================================
// Megakernel: one launch, spin-gated phases.
//   [0,2048)      build_adj  (2 rows/block, 2 warps/row, coalesced loads)
//   [2048,2304)   compute_Z  (16-row tiles)
//   [2304,2432)   Ut transpose
//   [2432,2442)   orth gram pairs
//   2442          orth-sum (waits prep)
//   [2443,6539)   attn       (waits prep)
//   [6539,7051)   finalize   (waits attn); last finisher resets counters
// ===========================================================================
extern "C" __global__ void __launch_bounds__(128, 8)
mega(const float* __restrict__ H, const float* __restrict__ mask,
     const float* __restrict__ U, const float* __restrict__ lp,
     const float* __restrict__ thr, float* __restrict__ out,
     float* __restrict__ loss_out, int want_loss)
{
    __shared__ __align__(16) char sbuf[19456];
    int b = blockIdx.x;
    int t = threadIdx.x;

    if (b < NB_ADJ) {
        // ---- build_adj: 2 rows/block, 2 warps/row. Coalesced: for each q the
        // warp reads 32 consecutive float4; bit b=q*4+j -> col q*128+lane*4+j.
        int* wtot_s = (int*)sbuf;
        int warp = t >> 5, lane = t & 31;
        int row  = b * 2 + (warp >> 1);
        int half = warp & 1;
        const float4* m4 = (const float4*)(mask + (size_t)row * Nn) + half * 512;

        unsigned mk[2];
        int pre[2], cb[2];
        int wtot = 0;
#pragma unroll
        for (int c = 0; c < 2; c++) {
            float4 v[8];
#pragma unroll
            for (int q = 0; q < 8; q++)
                v[q] = __ldcs(&m4[c * 256 + q * 32 + lane]);
            unsigned m = 0;
#pragma unroll
            for (int q = 0; q < 8; q++) {
                if (v[q].x > 0.5f) m |= 1u << (q * 4 + 0);
                if (v[q].y > 0.5f) m |= 1u << (q * 4 + 1);
                if (v[q].z > 0.5f) m |= 1u << (q * 4 + 2);
                if (v[q].w > 0.5f) m |= 1u << (q * 4 + 3);
            }
            int cnt = __popc(m);
            int p = cnt;
#pragma unroll
            for (int o = 1; o < 32; o <<= 1) {
                int nb = __shfl_up_sync(0xffffffffu, p, o);
                if (lane >= o) p += nb;
            }
            mk[c] = m; pre[c] = p; cb[c] = wtot;
            wtot += __shfl_sync(0xffffffffu, p, 31);
        }
        if (lane == 0) wtot_s[warp] = wtot;
        __syncthreads();
        int rowbase = half ? wtot_s[warp - 1] : 0;

#pragma unroll
        for (int c = 0; c < 2; c++) {
            int cnt  = __popc(mk[c]);
            int pos  = rowbase + cb[c] + pre[c] - cnt;
            int col0 = half * 2048 + c * 1024 + lane * 4;
            unsigned m = mk[c];
            while (m) {
                int bit = __ffs(m) - 1;
                m &= m - 1;
                int col = col0 + (bit >> 2) * 128 + (bit & 3);
                if (pos < MAXNBR) g_nbr[row][pos] = col;
                pos++;
            }
        }
        if (lane == 0 && half == 1) {
            int tot = rowbase + wtot;
            g_cnt[row] = tot < MAXNBR ? tot : MAXNBR;
        }
        __syncthreads();
        if (t == 0) { __threadfence(); red_rel_add(&g_prep_ctr, 1); }

    } else if (b < NB_ADJ + NB_Z) {
        // ---- compute_Z: Z2[i][ks] = sum_d H[i][d] * U[k][d][s], 16-row tile
        float (*Hs)[Dd] = (float (*)[Dd])sbuf;        // 16 KB
        int i0 = (b - NB_ADJ) * 16;
        const float4* Hf4 = (const float4*)H;
        float4* Hs4 = (float4*)&Hs[0][0];
#pragma unroll
        for (int q = 0; q < 8; q++)
            Hs4[q * 128 + t] = Hf4[(size_t)i0 * 64 + q * 128 + t];
        __syncthreads();

        int tx = t & 31, ty = t >> 5;                 // tx: ks4, ty: 4 row-groups
        int k = tx >> 3, s4 = tx & 7;
        const float4* Up = (const float4*)(U + ((size_t)k * Dd) * Ss + s4 * 4);
        int r0 = ty * 4;
        float4 a0 = {0,0,0,0}, a1 = {0,0,0,0}, a2 = {0,0,0,0}, a3 = {0,0,0,0};
#pragma unroll 4
        for (int d = 0; d < Dd; d++) {
            float4 u = Up[d * 8];
            fma4(a0, u, Hs[r0 + 0][d]);
            fma4(a1, u, Hs[r0 + 1][d]);
            fma4(a2, u, Hs[r0 + 2][d]);
            fma4(a3, u, Hs[r0 + 3][d]);
        }
        float4* Z4 = (float4*)&g_Z2[0][0];
        Z4[(size_t)(i0 + r0 + 0) * 32 + tx] = a0;
        Z4[(size_t)(i0 + r0 + 1) * 32 + tx] = a1;
        Z4[(size_t)(i0 + r0 + 2) * 32 + tx] = a2;
        Z4[(size_t)(i0 + r0 + 3) * 32 + tx] = a3;
        __syncthreads();
        if (t == 0) { __threadfence(); red_rel_add(&g_prep_ctr, 1); }

    } else if (b < NB_ADJ + NB_Z + NB_UT) {
        // ---- transpose U -> Ut[ks][d] ----
#pragma unroll
        for (int q = 0; q < 2; q++) {
            int idx = (b - NB_ADJ - NB_Z) * 256 + q * 128 + t;
            int k = idx >> 13;
            int r = idx & 8191;
            int d = r >> 5;
            int s = r & 31;
            g_Ut[k * Ss + s][d] = U[idx];
        }
        __syncthreads();
        if (t == 0) { __threadfence(); red_rel_add(&g_prep_ctr, 1); }

    } else if (b < N_PREP) {
        // ---- orth_pair p: gram block, 64-wide d-tiles, 128 threads ----
        float (*As)[65] = (float (*)[65])sbuf;                    // 8320 B
        float (*Bs)[65] = (float (*)[65])(sbuf + 8320);           // 8320 B
        float* red      = (float*)(sbuf + 16640);                 // 512 B
        int p = b - (NB_ADJ + NB_Z + NB_UT);
        int k = c_pk[p], l = c_pl[p];
        int a0 = (t >> 3) * 2;                        // 16 groups x 2 a's
        int b0 = (t & 7) * 4;                         // 8 groups x 4 b's
        float c00=0,c01=0,c02=0,c03=0,c10=0,c11=0,c12=0,c13=0;

        const float* Uk = U + (size_t)k * Dd * Ss;
        const float* Ul = U + (size_t)l * Dd * Ss;
        for (int d0 = 0; d0 < Dd; d0 += 64) {
            __syncthreads();
            for (int idx = t; idx < 32 * 64; idx += 128) {
                int d = idx >> 5, a = idx & 31;
                As[a][d] = Uk[(size_t)(d0 + d) * Ss + a];
                Bs[a][d] = Ul[(size_t)(d0 + d) * Ss + a];
            }
            __syncthreads();
#pragma unroll 4
            for (int d = 0; d < 64; d++) {
                float av0 = As[a0][d], av1 = As[a0 + 1][d];
                float bv0 = Bs[b0][d], bv1 = Bs[b0 + 1][d];
                float bv2 = Bs[b0 + 2][d], bv3 = Bs[b0 + 3][d];
                c00 += av0 * bv0; c01 += av0 * bv1; c02 += av0 * bv2; c03 += av0 * bv3;
                c10 += av1 * bv0; c11 += av1 * bv1; c12 += av1 * bv2; c13 += av1 * bv3;
            }
        }

        float local = 0.f;
        if (k == l) {
            float e;
            e = c00 - ((a0     == b0    ) ? 1.f : 0.f); local += e * e;
            e = c01 - ((a0     == b0 + 1) ? 1.f : 0.f); local += e * e;
            e = c02 - ((a0     == b0 + 2) ? 1.f : 0.f); local += e * e;
            e = c03 - ((a0     == b0 + 3) ? 1.f : 0.f); local += e * e;
            e = c10 - ((a0 + 1 == b0    ) ? 1.f : 0.f); local += e * e;
            e = c11 - ((a0 + 1 == b0 + 1) ? 1.f : 0.f); local += e * e;
            e = c12 - ((a0 + 1 == b0 + 2) ? 1.f : 0.f); local += e * e;
            e = c13 - ((a0 + 1 == b0 + 3) ? 1.f : 0.f); local += e * e;
        } else {
            local = c00*c00 + c01*c01 + c02*c02 + c03*c03
                  + c10*c10 + c11*c11 + c12*c12 + c13*c13;
        }
        red[t] = local;
        __syncthreads();
        for (int o = 64; o; o >>= 1) {
            if (t < o) red[t] += red[t + o];
            __syncthreads();
        }
        if (t == 0) {
            g_orth[p] = red[0];
            __threadfence();
            red_rel_add(&g_prep_ctr, 1);
        }

    } else if (b == B_E) {
        // ---- orth final sum: waits prep, participates in fin counter ----
        if (t == 0) {
            spin_until(&g_prep_ctr, N_PREP);
            float s = 0.f;
#pragma unroll
            for (int p = 0; p < 10; p++) s += g_orth[p];
            if (want_loss) loss_out[0] = s;
            __threadfence();
            int old = atom_rel_add(&g_fin_ctr, 1);
            if (old == FIN_PART - 1) { g_prep_ctr = 0; g_attn_ctr = 0; g_fin_ctr = 0; }
        }

    } else if (b < B_FIN0) {
        // ---- attn: online softmax, double-buffered full-tile prefetch ----
        int*   snbr = (int*)sbuf;                                  // 1024 B
        float (*Zt)[32][33] = (float (*)[32][33])(sbuf + 1024);    // 16896 B
        float (*ew)[32] = (float (*)[32])(sbuf + 17920);           // 512 B
        float (*zq)[Ss] = (float (*)[Ss])(sbuf + 18432);           // 512 B
        int* scnt = (int*)(sbuf + 18944);

        int i = b - B_ATTN0;
        int k = t >> 5, lane = t & 31;

        if (t == 0) spin_until(&g_prep_ctr, N_PREP);
        __syncthreads();
        __threadfence();

        if (t == 0) *scnt = g_cnt[i];
        zq[k][lane] = g_Z2[i][t] * __expf(lp[t]);    // t == k*32+lane
        for (int j = lane; j < 32 * 33; j += 32) (&Zt[k][0][0])[j] = 0.f;
        __syncthreads();
        int cnt = *scnt;
        for (int j = t; j < cnt; j += 128) snbr[j] = g_nbr[i][j];
        __syncthreads();

        const float inv = 0.17677669529663687f;      // 1/sqrt(32)
        int kbase = k << 5;
        int jj = lane >> 3;
        int cc = (lane & 7) * 4;
        float M = -3.0e38f, L = 0.f;
        float a0 = 0.f, a1 = 0.f, a2 = 0.f, a3 = 0.f;

        float4 pv[8];
#pragma unroll
        for (int it = 0; it < 8; it++) {
            int r = jj + 4 * it;
            if (r < cnt) pv[it] = *(const float4*)&g_Z2[snbr[r]][kbase + cc];
        }

        for (int t0 = 0; t0 < cnt; t0 += 32) {
            int tl = min(32, cnt - t0);

#pragma unroll
            for (int it = 0; it < 8; it++) {
                int r = jj + 4 * it;
                if (r < tl) {
                    Zt[k][r][cc + 0] = pv[it].x; Zt[k][r][cc + 1] = pv[it].y;
                    Zt[k][r][cc + 2] = pv[it].z; Zt[k][r][cc + 3] = pv[it].w;
                }
            }
            __syncwarp();

            int n0 = t0 + 32;
            if (n0 < cnt) {
#pragma unroll
                for (int it = 0; it < 8; it++) {
                    int r = n0 + jj + 4 * it;
                    if (r < cnt) pv[it] = *(const float4*)&g_Z2[snbr[r]][kbase + cc];
                }
            }

            float s0 = 0.f, s1 = 0.f;
#pragma unroll
            for (int s = 0; s < Ss; s += 2) {
                s0 += zq[k][s]     * Zt[k][lane][s];
                s1 += zq[k][s + 1] * Zt[k][lane][s + 1];
            }
            float sc = (lane < tl) ? (s0 + s1) * inv : -3.0e38f;

            float mt = sc;
#pragma unroll
            for (int o = 16; o; o >>= 1) mt = fmaxf(mt, __shfl_xor_sync(0xffffffffu, mt, o));
            float newM = fmaxf(M, mt);
            float e = (lane < tl) ? __expf(sc - newM) : 0.f;
            ew[k][lane] = e;
            float es = e;
#pragma unroll
            for (int o = 16; o; o >>= 1) es += __shfl_xor_sync(0xffffffffu, es, o);
            float scale = __expf(M - newM);
            L = L * scale + es;
            a0 *= scale; a1 *= scale; a2 *= scale; a3 *= scale;
            M = newM;
            __syncwarp();

#pragma unroll
            for (int j = 0; j < 32; j += 4) {
                a0 += ew[k][j + 0] * Zt[k][j + 0][lane];
                a1 += ew[k][j + 1] * Zt[k][j + 1][lane];
                a2 += ew[k][j + 2] * Zt[k][j + 2][lane];
                a3 += ew[k][j + 3] * Zt[k][j + 3][lane];
            }
            __syncwarp();
        }
        g_G2[i][t] = ((a0 + a1) + (a2 + a3)) / L;
        __syncthreads();
        if (t == 0) { __threadfence(); red_rel_add(&g_attn_ctr, 1); }

    } else {
        // ---- finalize: 8-row tile. thread = 4 rows x float4 of d ----
        float (*Gs)[KS] = (float (*)[KS])sbuf;       // 4 KB
        int fb = b - B_FIN0;
        int i0 = fb * 8;

        if (t == 0) spin_until(&g_attn_ctr, Nn);
        __syncthreads();
        __threadfence();

#pragma unroll
        for (int q = 0; q < 2; q++)
            ((float4*)&Gs[0][0])[q * 128 + t] =
                ((const float4*)&g_G2[0][0])[(size_t)i0 * 32 + q * 128 + t];
        __syncthreads();

        int tx = t & 63, ty = t >> 6;                // tx: d4 group, ty: row-group
        int r0 = ty * 4;
        float4 acc0 = {0,0,0,0}, acc1 = {0,0,0,0}, acc2 = {0,0,0,0}, acc3 = {0,0,0,0};
#pragma unroll 4
        for (int ks = 0; ks < KS; ks++) {
            float4 u = *(const float4*)&g_Ut[ks][tx * 4];
            fma4(acc0, u, Gs[r0 + 0][ks]);
            fma4(acc1, u, Gs[r0 + 1][ks]);
            fma4(acc2, u, Gs[r0 + 2][ks]);
            fma4(acc3, u, Gs[r0 + 3][ks]);
        }

        const float4* Hf4 = (const float4*)H;
        const float4* Tf4 = (const float4*)thr;
        float4* Of4 = (float4*)out;
        float4 th = Tf4[tx];
        float4 accs[4] = {acc0, acc1, acc2, acc3};
#pragma unroll
        for (int r = 0; r < 4; r++) {
            int i = i0 + r0 + r;
            float4 a = accs[r];
            float4 h = Hf4[(size_t)i * 64 + tx];
            float4 v;
            v.x = h.x + ETA * a.x;
            v.y = h.y + ETA * a.y;
            v.z = h.z + ETA * a.z;
            v.w = h.w + ETA * a.w;
            float m;
            m = fmaxf(fabsf(v.x) - th.x, 0.f); v.x = copysignf(m, v.x);
            m = fmaxf(fabsf(v.y) - th.y, 0.f); v.y = copysignf(m, v.y);
            m = fmaxf(fabsf(v.z) - th.z, 0.f); v.z = copysignf(m, v.z);
            m = fmaxf(fabsf(v.w) - th.w, 0.f); v.w = copysignf(m, v.w);
            Of4[(size_t)i * 64 + tx] = v;
        }
        __syncthreads();
        if (t == 0) {
            __threadfence();
            int old = atom_rel_add(&g_fin_ctr, 1);
            if (old == FIN_PART - 1) { g_prep_ctr = 0; g_attn_ctr = 0; g_fin_ctr = 0; }
        }
    }
}

// ---------------------------------------------------------------------------
extern "C" void kernel_launch(void* const* d_in, const int* in_sizes, int n_in,
                              void* d_out, int out_size) {
    const float* H    = (const float*)d_in[0];   // [N, D]
    const float* mask = (const float*)d_in[1];   // [N, N]
    const float* U    = (const float*)d_in[2];   // [K, D, S]
    const float* lp   = (const float*)d_in[3];   // [K, S]
    const float* thr  = (const float*)d_in[4];   // [D]
    float* out = (float*)d_out;

    int want_loss = (out_size > Nn * Dd) ? 1 : 0;
    mega<<<GRID, 128>>>(H, mask, U, lp, thr, out, out + (size_t)Nn * Dd, want_loss);
}